// round 2
// baseline (speedup 1.0000x reference)
#include <cuda_runtime.h>
#include <stdint.h>

#define BATCH   32
#define MAXN    100000
#define MAXM    100000
#define MAXNNZ  3200000
#define SCAN_T  1024
#define MAXBLK  128   // >= ceil(MAXM / SCAN_T)

__device__ float g_xT[(size_t)MAXN * BATCH];   // (N, B) x transposed
__device__ float g_yT[(size_t)MAXM * BATCH];   // (M, B) result before final transpose
__device__ int   g_counts[MAXM];               // histogram, then scatter cursor
__device__ int   g_offsets[MAXM];              // exclusive scan of counts
__device__ int2  g_edges[MAXNNZ];              // dst-sorted (src, val_bits)
__device__ int   g_blocksums[MAXBLK];

// ---------------------------------------------------------------------------
// 1) Transpose x: (B, N) -> (N, B), fused: zero the dst histogram.
// ---------------------------------------------------------------------------
__global__ void transpose_in_kernel(const float* __restrict__ x, int N, int M) {
    __shared__ float tile[32][33];
    const int n0 = blockIdx.x * 32;
    const int tx = threadIdx.x;   // 0..31
    const int ty = threadIdx.y;   // 0..7

    // fused: zero counts (grid has 3125*256 = 800K threads >= M)
    int lin = blockIdx.x * 256 + ty * 32 + tx;
    if (lin < M) g_counts[lin] = 0;

    #pragma unroll
    for (int i = 0; i < 32; i += 8) {
        int b = ty + i;
        int n = n0 + tx;
        tile[b][tx] = (n < N) ? x[(size_t)b * N + n] : 0.0f;
    }
    __syncthreads();
    #pragma unroll
    for (int i = 0; i < 32; i += 8) {
        int n = n0 + ty + i;
        if (n < N) g_xT[(size_t)n * BATCH + tx] = tile[tx][ty + i];
    }
}

// ---------------------------------------------------------------------------
// 2) Histogram of dst
// ---------------------------------------------------------------------------
__global__ void histogram_kernel(const int* __restrict__ dst, int nnz) {
    int e = blockIdx.x * blockDim.x + threadIdx.x;
    if (e < nnz) atomicAdd(&g_counts[dst[e]], 1);
}

// ---------------------------------------------------------------------------
// 3) Exclusive scan of counts -> offsets (3 kernels)
// ---------------------------------------------------------------------------
__global__ void scan1_kernel(int M) {
    __shared__ int sh[SCAN_T];
    int i = blockIdx.x * SCAN_T + threadIdx.x;
    int v = (i < M) ? g_counts[i] : 0;
    sh[threadIdx.x] = v;
    __syncthreads();
    #pragma unroll
    for (int off = 1; off < SCAN_T; off <<= 1) {
        int t = (threadIdx.x >= off) ? sh[threadIdx.x - off] : 0;
        __syncthreads();
        sh[threadIdx.x] += t;
        __syncthreads();
    }
    if (i < M) g_offsets[i] = sh[threadIdx.x] - v;   // exclusive
    if (threadIdx.x == SCAN_T - 1) g_blocksums[blockIdx.x] = sh[threadIdx.x];
}

__global__ void scan2_kernel(int nblocks) {
    __shared__ int sh[MAXBLK];
    int v = (threadIdx.x < nblocks) ? g_blocksums[threadIdx.x] : 0;
    sh[threadIdx.x] = v;
    __syncthreads();
    #pragma unroll
    for (int off = 1; off < MAXBLK; off <<= 1) {
        int t = (threadIdx.x >= off) ? sh[threadIdx.x - off] : 0;
        __syncthreads();
        sh[threadIdx.x] += t;
        __syncthreads();
    }
    if (threadIdx.x < nblocks) g_blocksums[threadIdx.x] = sh[threadIdx.x] - v;
}

__global__ void scan3_kernel(int M) {
    int i = blockIdx.x * blockDim.x + threadIdx.x;
    if (i < M) {
        int o = g_offsets[i] + g_blocksums[i >> 10];
        g_offsets[i] = o;
        g_counts[i]  = o;   // becomes scatter cursor
    }
}

// ---------------------------------------------------------------------------
// 4) Scatter edges into dst-sorted order
// ---------------------------------------------------------------------------
__global__ void scatter_kernel(const int* __restrict__ src,
                               const int* __restrict__ dst,
                               const float* __restrict__ val,
                               int nnz) {
    int e = blockIdx.x * blockDim.x + threadIdx.x;
    if (e < nnz) {
        int d = dst[e];
        int pos = atomicAdd(&g_counts[d], 1);
        g_edges[pos] = make_int2(src[e], __float_as_int(val[e]));
    }
}

// ---------------------------------------------------------------------------
// 5) Accumulate: one warp per output row m. 4 edge-groups of 8 lanes each;
//    each lane owns float4 (4 batches). Register accumulation, shfl reduce,
//    bias add, one 128B plain store. NO global atomics.
// ---------------------------------------------------------------------------
__global__ void accumulate_kernel(const float* __restrict__ bias,
                                  int M, int nnz) {
    const int warp = (blockIdx.x * blockDim.x + threadIdx.x) >> 5;
    if (warp >= M) return;
    const int m    = warp;
    const int lane = threadIdx.x & 31;
    const int g    = lane >> 3;   // edge group 0..3
    const int sub  = lane & 7;    // float4 slot 0..7

    const int beg = g_offsets[m];
    const int end = (m + 1 < M) ? g_offsets[m + 1] : nnz;

    float4 acc = make_float4(0.f, 0.f, 0.f, 0.f);
    for (int e = beg + g; e < end; e += 4) {
        const int2 sv = __ldg(&g_edges[e]);
        const float v = __int_as_float(sv.y);
        const float4 xv = *reinterpret_cast<const float4*>(
            g_xT + (size_t)sv.x * BATCH + sub * 4);
        acc.x = fmaf(v, xv.x, acc.x);
        acc.y = fmaf(v, xv.y, acc.y);
        acc.z = fmaf(v, xv.z, acc.z);
        acc.w = fmaf(v, xv.w, acc.w);
    }

    // reduce the 4 edge-groups (lanes sub, sub+8, sub+16, sub+24)
    #pragma unroll
    for (int off = 8; off <= 16; off <<= 1) {
        acc.x += __shfl_xor_sync(0xffffffff, acc.x, off);
        acc.y += __shfl_xor_sync(0xffffffff, acc.y, off);
        acc.z += __shfl_xor_sync(0xffffffff, acc.z, off);
        acc.w += __shfl_xor_sync(0xffffffff, acc.w, off);
    }

    if (g == 0) {
        const float b = __ldg(bias + m);
        float4 r = make_float4(acc.x + b, acc.y + b, acc.z + b, acc.w + b);
        *reinterpret_cast<float4*>(g_yT + (size_t)m * BATCH + sub * 4) = r;
    }
}

// ---------------------------------------------------------------------------
// 6) Transpose out: (M, B) -> (B, M)
// ---------------------------------------------------------------------------
__global__ void transpose_out_kernel(float* __restrict__ out, int M) {
    __shared__ float tile[32][33];
    const int m0 = blockIdx.x * 32;
    const int tx = threadIdx.x;
    const int ty = threadIdx.y;
    #pragma unroll
    for (int i = 0; i < 32; i += 8) {
        int m = m0 + ty + i;
        if (m < M) tile[ty + i][tx] = g_yT[(size_t)m * BATCH + tx];
    }
    __syncthreads();
    #pragma unroll
    for (int i = 0; i < 32; i += 8) {
        int b = ty + i;
        int m = m0 + tx;
        if (m < M) out[(size_t)b * M + m] = tile[tx][b];
    }
}

// ---------------------------------------------------------------------------
// kernel_launch
// Inputs: x (B*N f32), indices (2*NNZ i32), values (NNZ f32), bias (M f32).
// Output: (B, M) f32.
// ---------------------------------------------------------------------------
extern "C" void kernel_launch(void* const* d_in, const int* in_sizes, int n_in,
                              void* d_out, int out_size) {
    const float* x       = (const float*)d_in[0];
    const int*   indices = (const int*)  d_in[1];
    const float* values  = (const float*)d_in[2];
    const float* bias    = (const float*)d_in[3];
    float*       out     = (float*)d_out;

    const int N   = in_sizes[0] / BATCH;
    const int nnz = in_sizes[1] / 2;
    const int M   = in_sizes[3];

    const int* src = indices;
    const int* dst = indices + nnz;

    dim3 tb(32, 8);
    const int nScanBlocks = (M + SCAN_T - 1) / SCAN_T;

    transpose_in_kernel<<<(N + 31) / 32, tb>>>(x, N, M);
    histogram_kernel<<<(nnz + 255) / 256, 256>>>(dst, nnz);
    scan1_kernel<<<nScanBlocks, SCAN_T>>>(M);
    scan2_kernel<<<1, MAXBLK>>>(nScanBlocks);
    scan3_kernel<<<(M + 255) / 256, 256>>>(M);
    scatter_kernel<<<(nnz + 255) / 256, 256>>>(src, dst, values, nnz);
    accumulate_kernel<<<(M * 32 + 255) / 256, 256>>>(bias, M, nnz);
    transpose_out_kernel<<<(M + 31) / 32, tb>>>(out, M);
}